// round 3
// baseline (speedup 1.0000x reference)
#include <cuda_runtime.h>

#define NTOK   8192     // 8 * 1024 tokens
#define DMODEL 1024
#define NQKV   512      // H * D_K
#define SEQ    1024
#define NHEAD  8
#define DHEAD  64

// Scratch (static device globals: allocation-guard safe)
__device__ float g_Q[NTOK * NQKV];
__device__ float g_K[NTOK * NQKV];
__device__ float g_V[NTOK * NQKV];
__device__ float g_AO[NTOK * NQKV];

// ---------------- packed f32x2 helpers (B300: full-rate fp32 FMA path) ---------
__device__ __forceinline__ unsigned long long pack2(float lo, float hi) {
    unsigned long long r;
    asm("mov.b64 %0, {%1, %2};" : "=l"(r) : "f"(lo), "f"(hi));
    return r;
}
__device__ __forceinline__ unsigned long long fma2(unsigned long long a,
                                                   unsigned long long b,
                                                   unsigned long long c) {
    unsigned long long d;
    asm("fma.rn.f32x2 %0, %1, %2, %3;" : "=l"(d) : "l"(a), "l"(b), "l"(c));
    return d;
}
__device__ __forceinline__ float2 unpack2(unsigned long long v) {
    float lo, hi;
    asm("mov.b64 {%0, %1}, %2;" : "=f"(lo), "=f"(hi) : "l"(v));
    return make_float2(lo, hi);
}

// ---------------- SGEMM: C[M,N] = A[M,K] @ B[K,N] + bias -----------------------
// BM=BN=128, BK=8, 256 threads, 8x8 per-thread tile, f32x2 packed accumulators.
__global__ __launch_bounds__(256, 2)
void sgemm_bias(const float* __restrict__ A, const float* __restrict__ B,
                const float* __restrict__ bias, float* __restrict__ C,
                int M, int N, int K) {
    __shared__ float As[8][128];   // [k][m] (A staged transposed)
    __shared__ float Bs[8][128];   // [k][n]
    const int tid = threadIdx.x;
    const int bx = blockIdx.x, by = blockIdx.y;

    const int aRow = tid >> 1;          // 0..127
    const int aCol = (tid & 1) << 2;    // 0 or 4
    const int bRow = tid >> 5;          // 0..7
    const int bCol = (tid & 31) << 2;   // 0..124
    const int tRow = (tid >> 4) << 3;   // 0..120
    const int tCol = (tid & 15) << 3;   // 0..120

    const float* Ab = A + (size_t)by * 128 * K;
    const float* Bb = B + bx * 128;

    unsigned long long acc[8][4];
#pragma unroll
    for (int i = 0; i < 8; i++)
#pragma unroll
        for (int j = 0; j < 4; j++) acc[i][j] = 0ull;

    for (int k0 = 0; k0 < K; k0 += 8) {
        float4 av = *(const float4*)(Ab + (size_t)aRow * K + k0 + aCol);
        As[aCol + 0][aRow] = av.x;
        As[aCol + 1][aRow] = av.y;
        As[aCol + 2][aRow] = av.z;
        As[aCol + 3][aRow] = av.w;
        *(float4*)&Bs[bRow][bCol] =
            *(const float4*)(Bb + (size_t)(k0 + bRow) * N + bCol);
        __syncthreads();
#pragma unroll
        for (int kk = 0; kk < 8; ++kk) {
            float4 b01 = *(const float4*)&Bs[kk][tCol];
            float4 b23 = *(const float4*)&Bs[kk][tCol + 4];
            unsigned long long b2[4] = { pack2(b01.x, b01.y), pack2(b01.z, b01.w),
                                         pack2(b23.x, b23.y), pack2(b23.z, b23.w) };
            float4 a01 = *(const float4*)&As[kk][tRow];
            float4 a23 = *(const float4*)&As[kk][tRow + 4];
            float a[8] = { a01.x, a01.y, a01.z, a01.w,
                           a23.x, a23.y, a23.z, a23.w };
#pragma unroll
            for (int i = 0; i < 8; i++) {
                unsigned long long a2 = pack2(a[i], a[i]);
#pragma unroll
                for (int j = 0; j < 4; j++) acc[i][j] = fma2(a2, b2[j], acc[i][j]);
            }
        }
        __syncthreads();
    }

    const float* bptr = bias + bx * 128 + tCol;
    float bv[8];
#pragma unroll
    for (int j = 0; j < 8; j++) bv[j] = bptr[j];
#pragma unroll
    for (int i = 0; i < 8; i++) {
        float* crow = C + (size_t)(by * 128 + tRow + i) * N + bx * 128 + tCol;
        float2 v0 = unpack2(acc[i][0]), v1 = unpack2(acc[i][1]);
        float2 v2 = unpack2(acc[i][2]), v3 = unpack2(acc[i][3]);
        float4 o0 = make_float4(v0.x + bv[0], v0.y + bv[1], v1.x + bv[2], v1.y + bv[3]);
        float4 o1 = make_float4(v2.x + bv[4], v2.y + bv[5], v3.x + bv[6], v3.y + bv[7]);
        *(float4*)crow = o0;
        *(float4*)(crow + 4) = o1;
    }
}

// ---------------- Flash attention: one block per (b, h, 64-query tile) ---------
// 256 threads; per thread a 4x4 tile (rows r0..r0+3, cols c0..c0+3).
// smem: Qs[d][q] 16KB + Ks[d][kv] 16KB + Vs[kv][d] 16KB + Ps[kv][q,pad68] 17KB.
#define ATTN_SMEM_FLOATS (64 * 64 * 3 + 64 * 68 + 192)
#define ATTN_SMEM_BYTES  (ATTN_SMEM_FLOATS * 4)

__global__ __launch_bounds__(256, 2)
void attn_kernel(const float* __restrict__ Qg, const float* __restrict__ Kg,
                 const float* __restrict__ Vg, float* __restrict__ Og) {
    extern __shared__ float sm[];
    float* Qs    = sm;                 // [64 d][64 q]
    float* Ks    = Qs + 64 * 64;       // [64 d][64 kv]
    float* Vs    = Ks + 64 * 64;       // [64 kv][64 d]
    float* Ps    = Vs + 64 * 64;       // [64 kv][68]  (pad for LDS.128 + banks)
    float* row_m = Ps + 64 * 68;       // [64]
    float* row_l = row_m + 64;         // [64]
    float* row_c = row_l + 64;         // [64] correction factors

    const int tid = threadIdx.x;
    const int q0  = blockIdx.x * 64;
    const int h   = blockIdx.y;
    const int b   = blockIdx.z;
    const size_t base = (size_t)b * SEQ;
    const int coff = h * DHEAD;

    // Load Q tile transposed: thread -> row r = tid/4, 16 d-values
    {
        int r = tid >> 2;
        int d0 = (tid & 3) << 4;
        const float* src = Qg + (base + q0 + r) * NQKV + coff + d0;
#pragma unroll
        for (int k = 0; k < 16; k += 4) {
            float4 v = *(const float4*)(src + k);
            Qs[(d0 + k + 0) * 64 + r] = v.x;
            Qs[(d0 + k + 1) * 64 + r] = v.y;
            Qs[(d0 + k + 2) * 64 + r] = v.z;
            Qs[(d0 + k + 3) * 64 + r] = v.w;
        }
    }
    if (tid < 64) { row_m[tid] = -1e30f; row_l[tid] = 0.0f; }

    const int r0 = (tid >> 4) << 2;       // output/query rows
    const int c0 = (tid & 15) << 2;       // kv cols (S phase) / d cols (PV phase)
    const bool leader = (tid & 15) == 0;

    float acc[4][4] = {};
    const float scale = 0.125f;           // 1/sqrt(64)

    for (int kv0 = 0; kv0 < SEQ; kv0 += 64) {
        __syncthreads();   // protect smem before overwrite (and Q load, 1st iter)
        {
            int r = tid >> 2;
            int d0 = (tid & 3) << 4;
            const float* ksrc = Kg + (base + kv0 + r) * NQKV + coff + d0;
            const float* vsrc = Vg + (base + kv0 + r) * NQKV + coff + d0;
#pragma unroll
            for (int k = 0; k < 16; k += 4) {
                float4 v = *(const float4*)(ksrc + k);
                Ks[(d0 + k + 0) * 64 + r] = v.x;
                Ks[(d0 + k + 1) * 64 + r] = v.y;
                Ks[(d0 + k + 2) * 64 + r] = v.z;
                Ks[(d0 + k + 3) * 64 + r] = v.w;
                *(float4*)&Vs[r * 64 + d0 + k] = *(const float4*)(vsrc + k);
            }
        }
        __syncthreads();

        // S = scale * Q @ K^T   (64x64x64, 4x4 per thread)
        float s[4][4] = {};
#pragma unroll 4
        for (int d = 0; d < 64; ++d) {
            float4 qa = *(const float4*)&Qs[d * 64 + r0];
            float4 kb = *(const float4*)&Ks[d * 64 + c0];
            float a[4]  = { qa.x, qa.y, qa.z, qa.w };
            float bb[4] = { kb.x, kb.y, kb.z, kb.w };
#pragma unroll
            for (int i = 0; i < 4; i++)
#pragma unroll
                for (int j = 0; j < 4; j++) s[i][j] += a[i] * bb[j];
        }

        float tmax[4], nm[4], om[4], psum[4];
#pragma unroll
        for (int i = 0; i < 4; i++) {
#pragma unroll
            for (int j = 0; j < 4; j++) s[i][j] *= scale;
            tmax[i] = fmaxf(fmaxf(s[i][0], s[i][1]), fmaxf(s[i][2], s[i][3]));
        }
        // row reduce over the 16 threads sharing this row group (one warp half)
#pragma unroll
        for (int off = 1; off < 16; off <<= 1)
#pragma unroll
            for (int i = 0; i < 4; i++)
                tmax[i] = fmaxf(tmax[i], __shfl_xor_sync(0xffffffffu, tmax[i], off));

#pragma unroll
        for (int i = 0; i < 4; i++) {
            om[i] = row_m[r0 + i];            // all reads precede leader's write
            nm[i] = fmaxf(om[i], tmax[i]);    // (shfl below reconverges the warp)
        }
#pragma unroll
        for (int i = 0; i < 4; i++) {
            float ps = 0.0f;
#pragma unroll
            for (int j = 0; j < 4; j++) {
                float p = __expf(s[i][j] - nm[i]);
                Ps[(c0 + j) * 68 + r0 + i] = p;   // transposed store
                ps += p;
            }
            psum[i] = ps;
        }
#pragma unroll
        for (int off = 1; off < 16; off <<= 1)
#pragma unroll
            for (int i = 0; i < 4; i++)
                psum[i] += __shfl_xor_sync(0xffffffffu, psum[i], off);

        if (leader) {
#pragma unroll
            for (int i = 0; i < 4; i++) {
                float corr = __expf(om[i] - nm[i]);
                row_c[r0 + i] = corr;
                row_m[r0 + i] = nm[i];
                row_l[r0 + i] = row_l[r0 + i] * corr + psum[i];
            }
        }
        __syncthreads();   // Ps + row_c visible

        // O = O*corr + P @ V   (64x64x64, 4x4 per thread)
#pragma unroll
        for (int i = 0; i < 4; i++) {
            float corr = row_c[r0 + i];
#pragma unroll
            for (int j = 0; j < 4; j++) acc[i][j] *= corr;
        }
#pragma unroll 4
        for (int kv = 0; kv < 64; ++kv) {
            float4 pa = *(const float4*)&Ps[kv * 68 + r0];
            float4 vb = *(const float4*)&Vs[kv * 64 + c0];
            float a[4]  = { pa.x, pa.y, pa.z, pa.w };
            float bb[4] = { vb.x, vb.y, vb.z, vb.w };
#pragma unroll
            for (int i = 0; i < 4; i++)
#pragma unroll
                for (int j = 0; j < 4; j++) acc[i][j] += a[i] * bb[j];
        }
    }

    // epilogue: divide by running sum, write [token][h*64 + d]
#pragma unroll
    for (int i = 0; i < 4; i++) {
        float inv = 1.0f / row_l[r0 + i];
        float4 o = make_float4(acc[i][0] * inv, acc[i][1] * inv,
                               acc[i][2] * inv, acc[i][3] * inv);
        *(float4*)&Og[(base + q0 + r0 + i) * NQKV + coff + c0] = o;
    }
}

// ---------------- launch -------------------------------------------------------
extern "C" void kernel_launch(void* const* d_in, const int* in_sizes, int n_in,
                              void* d_out, int out_size) {
    const float* x  = (const float*)d_in[0];
    const float* Wq = (const float*)d_in[1];
    const float* bq = (const float*)d_in[2];
    const float* Wk = (const float*)d_in[3];
    const float* bk = (const float*)d_in[4];
    const float* Wv = (const float*)d_in[5];
    const float* bv = (const float*)d_in[6];
    const float* Wo = (const float*)d_in[7];
    const float* bo = (const float*)d_in[8];
    float* out = (float*)d_out;

    float *Qd, *Kd, *Vd, *AOd;
    cudaGetSymbolAddress((void**)&Qd,  g_Q);
    cudaGetSymbolAddress((void**)&Kd,  g_K);
    cudaGetSymbolAddress((void**)&Vd,  g_V);
    cudaGetSymbolAddress((void**)&AOd, g_AO);

    // >48KB dynamic smem opt-in (idempotent; persists from the correctness call)
    cudaFuncSetAttribute(attn_kernel,
                         cudaFuncAttributeMaxDynamicSharedMemorySize,
                         ATTN_SMEM_BYTES);

    dim3 blk(256);

    // QKV projections: [8192,1024] @ [1024,512]
    dim3 g1(NQKV / 128, NTOK / 128);
    sgemm_bias<<<g1, blk>>>(x, Wq, bq, Qd, NTOK, NQKV, DMODEL);
    sgemm_bias<<<g1, blk>>>(x, Wk, bk, Kd, NTOK, NQKV, DMODEL);
    sgemm_bias<<<g1, blk>>>(x, Wv, bv, Vd, NTOK, NQKV, DMODEL);

    // attention
    dim3 ga(SEQ / 64, NHEAD, 8);
    attn_kernel<<<ga, blk, ATTN_SMEM_BYTES>>>(Qd, Kd, Vd, AOd);

    // output projection: [8192,512] @ [512,1024] -> d_out
    dim3 g2(DMODEL / 128, NTOK / 128);
    sgemm_bias<<<g2, blk>>>(AOd, Wo, bo, out, NTOK, DMODEL, NQKV);
}

// round 5
// speedup vs baseline: 1.3605x; 1.3605x over previous
#include <cuda_runtime.h>
#include <cuda_bf16.h>
#include <cstdint>

#define NTOK   8192     // 8 * 1024 tokens
#define DMODEL 1024
#define NQKV   512      // H * D_K
#define SEQ    1024
#define NHEAD  8
#define DHEAD  64

// -------------------- scratch (device globals: allocation-guard safe) ----------
__device__ float g_Q[NTOK * NQKV];
__device__ float g_K[NTOK * NQKV];
__device__ float g_V[NTOK * NQKV];
__device__ float g_AO[NTOK * NQKV];

__device__ __nv_bfloat16 g_xh[NTOK * DMODEL], g_xl[NTOK * DMODEL];
__device__ __nv_bfloat16 g_aoh[NTOK * NQKV],  g_aol[NTOK * NQKV];
__device__ __nv_bfloat16 g_wqh[NQKV * DMODEL], g_wql[NQKV * DMODEL];
__device__ __nv_bfloat16 g_wkh[NQKV * DMODEL], g_wkl[NQKV * DMODEL];
__device__ __nv_bfloat16 g_wvh[NQKV * DMODEL], g_wvl[NQKV * DMODEL];
__device__ __nv_bfloat16 g_woh[DMODEL * NQKV], g_wol[DMODEL * NQKV];

// single file-scope dynamic smem symbol shared by all kernels
extern __shared__ unsigned char dynsmem[];

// -------------------- PTX helpers (all base-target sm_80+ instructions) --------
__device__ __forceinline__ uint32_t smem_to_u32(const void* p) {
    uint32_t a;
    asm("{ .reg .u64 t; cvta.to.shared.u64 t, %1; cvt.u32.u64 %0, t; }"
        : "=r"(a) : "l"(p));
    return a;
}
__device__ __forceinline__ void cp16(uint32_t dst, const void* src) {
    asm volatile("cp.async.ca.shared.global [%0], [%1], 16;"
                 :: "r"(dst), "l"(src) : "memory");
}
#define CP_COMMIT() asm volatile("cp.async.commit_group;" ::: "memory")
#define CP_WAIT1()  asm volatile("cp.async.wait_group 1;" ::: "memory")
#define CP_WAIT0()  asm volatile("cp.async.wait_group 0;" ::: "memory")

__device__ __forceinline__ void ldsm_x4(uint32_t* r, uint32_t addr) {
    asm volatile("ldmatrix.sync.aligned.m8n8.x4.shared.b16 {%0,%1,%2,%3}, [%4];"
                 : "=r"(r[0]), "=r"(r[1]), "=r"(r[2]), "=r"(r[3]) : "r"(addr));
}
__device__ __forceinline__ void ldsm_x2(uint32_t* r, uint32_t addr) {
    asm volatile("ldmatrix.sync.aligned.m8n8.x2.shared.b16 {%0,%1}, [%2];"
                 : "=r"(r[0]), "=r"(r[1]) : "r"(addr));
}
__device__ __forceinline__ void mma16816(float* c, const uint32_t* a, const uint32_t* b) {
    asm volatile("mma.sync.aligned.m16n8k16.row.col.f32.bf16.bf16.f32 "
                 "{%0,%1,%2,%3}, {%4,%5,%6,%7}, {%8,%9}, {%0,%1,%2,%3};"
                 : "+f"(c[0]), "+f"(c[1]), "+f"(c[2]), "+f"(c[3])
                 : "r"(a[0]), "r"(a[1]), "r"(a[2]), "r"(a[3]),
                   "r"(b[0]), "r"(b[1]));
}

// -------------------- pre-pass: split fp32 -> bf16 hi/lo -----------------------
__global__ void split_kernel(const float* __restrict__ src,
                             __nv_bfloat16* __restrict__ hi,
                             __nv_bfloat16* __restrict__ lo, int n2) {
    int i = blockIdx.x * blockDim.x + threadIdx.x;
    if (i < n2) {
        float2 v = ((const float2*)src)[i];
        __nv_bfloat16 h0 = __float2bfloat16(v.x);
        __nv_bfloat16 h1 = __float2bfloat16(v.y);
        __nv_bfloat16 l0 = __float2bfloat16(v.x - __bfloat162float(h0));
        __nv_bfloat16 l1 = __float2bfloat16(v.y - __bfloat162float(h1));
        ((__nv_bfloat162*)hi)[i] = __halves2bfloat162(h0, h1);
        ((__nv_bfloat162*)lo)[i] = __halves2bfloat162(l0, l1);
    }
}

// -------------------- pre-pass: W[K,N] fp32 -> Wt[N,K] bf16 hi/lo --------------
__global__ void transpose_split(const float* __restrict__ W,
                                __nv_bfloat16* __restrict__ Th,
                                __nv_bfloat16* __restrict__ Tl, int Kd, int Nd) {
    __shared__ float t[32][33];
    int k0 = blockIdx.y * 32, n0 = blockIdx.x * 32;
    for (int i = threadIdx.y; i < 32; i += 8)
        t[i][threadIdx.x] = W[(size_t)(k0 + i) * Nd + n0 + threadIdx.x];
    __syncthreads();
    for (int i = threadIdx.y; i < 32; i += 8) {
        float v = t[threadIdx.x][i];   // = W[k0+tx][n0+i]
        __nv_bfloat16 h = __float2bfloat16(v);
        __nv_bfloat16 l = __float2bfloat16(v - __bfloat162float(h));
        size_t o = (size_t)(n0 + i) * Kd + k0 + threadIdx.x;
        Th[o] = h; Tl[o] = l;
    }
}

// -------------------- bf16x3 HMMA GEMM: C[M,N] = A[M,K] @ B[N,K]^T + bias ------
// CTA tile 128x128, BK=32, 8 warps (64x32 warp tiles), double-buffered cp.async.
// smem rows padded to 80 B (40 bf16): conflict-free ldmatrix (20-bank stride).
#define GASTRIDE   40                       // bf16 elems per smem row
#define GMAT_BYTES (128 * GASTRIDE * 2)     // 10240 B per matrix tile
#define GSTAGE     (4 * GMAT_BYTES)         // Ah, Al, Bh, Bl = 40960 B
#define GSM_TOTAL  (2 * GSTAGE)             // double buffer = 81920 B

__global__ __launch_bounds__(256)
void gemm_bf16x3(const __nv_bfloat16* __restrict__ Ah, const __nv_bfloat16* __restrict__ Al,
                 const __nv_bfloat16* __restrict__ Bh, const __nv_bfloat16* __restrict__ Bl,
                 const float* __restrict__ bias, float* __restrict__ C, int K, int N) {
    const uint32_t smem_base = smem_to_u32(dynsmem);
    const int tid  = threadIdx.x;
    const int wid  = tid >> 5, lane = tid & 31;
    const int m0 = blockIdx.y * 128, n0 = blockIdx.x * 128;

    // ---- loader mapping: 64 threads per matrix, 2 rows each, 4x16B per row ----
    const int mat = tid >> 6;           // 0=Ah 1=Al 2=Bh 3=Bl
    const int rr  = tid & 63;
    const __nv_bfloat16* mats[4] = { Ah, Al, Bh, Bl };
    const int brow = (mat < 2) ? m0 : n0;
    const __nv_bfloat16* gsrc = mats[mat] + (size_t)brow * K;
    const uint32_t sdst = smem_base + mat * GMAT_BYTES;

    // ---- compute mapping -------------------------------------------------------
    const int wm = (wid & 1) * 64;
    const int wn = (wid >> 1) * 32;
    const int aRowOff = (lane & 7) + ((lane & 8) ? 8 : 0);
    const int aColOff = (lane & 16) ? 8 : 0;
    const int bRowOff = (lane & 7);
    const int bColOff = (lane & 8) ? 8 : 0;   // lanes 16-31: addr ignored by x2

    float acc[4][4][4];
#pragma unroll
    for (int i = 0; i < 4; i++)
#pragma unroll
        for (int j = 0; j < 4; j++)
#pragma unroll
            for (int c = 0; c < 4; c++) acc[i][j][c] = 0.0f;

    const int nstage = K >> 5;

    // prologue: stage 0
    {
#pragma unroll
        for (int h = 0; h < 2; ++h) {
            int row = rr + h * 64;
            const __nv_bfloat16* src = gsrc + (size_t)row * K;
            uint32_t d = sdst + row * (GASTRIDE * 2);
#pragma unroll
            for (int c = 0; c < 4; ++c) cp16(d + c * 16, src + c * 8);
        }
        CP_COMMIT();
    }

    for (int s = 0; s < nstage; ++s) {
        if (s + 1 < nstage) {
            const int k0 = (s + 1) << 5;
            const uint32_t boff = ((s + 1) & 1) * GSTAGE;
#pragma unroll
            for (int h = 0; h < 2; ++h) {
                int row = rr + h * 64;
                const __nv_bfloat16* src = gsrc + (size_t)row * K + k0;
                uint32_t d = sdst + boff + row * (GASTRIDE * 2);
#pragma unroll
                for (int c = 0; c < 4; ++c) cp16(d + c * 16, src + c * 8);
            }
            CP_COMMIT();
            CP_WAIT1();
        } else {
            CP_WAIT0();
        }
        __syncthreads();

        const uint32_t sb = smem_base + (s & 1) * GSTAGE;
        const uint32_t sbB = sb + 2 * GMAT_BYTES;
#pragma unroll
        for (int kc = 0; kc < 32; kc += 16) {
            uint32_t ah[4][4], al[4][4], bh[4][2], bl[4][2];
#pragma unroll
            for (int i = 0; i < 4; ++i) {
                uint32_t addr = sb + (wm + 16 * i + aRowOff) * (GASTRIDE * 2)
                                   + (kc + aColOff) * 2;
                ldsm_x4(ah[i], addr);
                ldsm_x4(al[i], addr + GMAT_BYTES);
            }
#pragma unroll
            for (int j = 0; j < 4; ++j) {
                uint32_t addr = sbB + (wn + 8 * j + bRowOff) * (GASTRIDE * 2)
                                    + (kc + bColOff) * 2;
                ldsm_x2(bh[j], addr);
                ldsm_x2(bl[j], addr + GMAT_BYTES);
            }
#pragma unroll
            for (int i = 0; i < 4; ++i)
#pragma unroll
                for (int j = 0; j < 4; ++j) {
                    mma16816(acc[i][j], ah[i], bh[j]);
                    mma16816(acc[i][j], ah[i], bl[j]);
                    mma16816(acc[i][j], al[i], bh[j]);
                }
        }
        __syncthreads();
    }

    // ---- epilogue: add bias, store fp32 ---------------------------------------
    const int er = lane >> 2;
    const int ec = (lane & 3) * 2;
#pragma unroll
    for (int j = 0; j < 4; ++j) {
        const int n = n0 + wn + 8 * j + ec;
        const float b0 = bias[n], b1 = bias[n + 1];
#pragma unroll
        for (int i = 0; i < 4; ++i) {
            const int m = m0 + wm + 16 * i + er;
            float2 v0 = make_float2(acc[i][j][0] + b0, acc[i][j][1] + b1);
            float2 v1 = make_float2(acc[i][j][2] + b0, acc[i][j][3] + b1);
            *(float2*)(C + (size_t)m * N + n)       = v0;
            *(float2*)(C + (size_t)(m + 8) * N + n) = v1;
        }
    }
}

// -------------------- Flash attention (unchanged, validated @546us) ------------
#define ATTN_SMEM_FLOATS (64 * 64 * 3 + 64 * 68 + 192)
#define ATTN_SMEM_BYTES  (ATTN_SMEM_FLOATS * 4)

__global__ __launch_bounds__(256, 2)
void attn_kernel(const float* __restrict__ Qg, const float* __restrict__ Kg,
                 const float* __restrict__ Vg, float* __restrict__ Og) {
    float* sm = (float*)dynsmem;
    float* Qs    = sm;
    float* Ks    = Qs + 64 * 64;
    float* Vs    = Ks + 64 * 64;
    float* Ps    = Vs + 64 * 64;
    float* row_m = Ps + 64 * 68;
    float* row_l = row_m + 64;
    float* row_c = row_l + 64;

    const int tid = threadIdx.x;
    const int q0  = blockIdx.x * 64;
    const int h   = blockIdx.y;
    const int b   = blockIdx.z;
    const size_t base = (size_t)b * SEQ;
    const int coff = h * DHEAD;

    {
        int rr = tid >> 2;
        int d0 = (tid & 3) << 4;
        const float* src = Qg + (base + q0 + rr) * NQKV + coff + d0;
#pragma unroll
        for (int k = 0; k < 16; k += 4) {
            float4 v = *(const float4*)(src + k);
            Qs[(d0 + k + 0) * 64 + rr] = v.x;
            Qs[(d0 + k + 1) * 64 + rr] = v.y;
            Qs[(d0 + k + 2) * 64 + rr] = v.z;
            Qs[(d0 + k + 3) * 64 + rr] = v.w;
        }
    }
    if (tid < 64) { row_m[tid] = -1e30f; row_l[tid] = 0.0f; }

    const int r0 = (tid >> 4) << 2;
    const int c0 = (tid & 15) << 2;
    const bool leader = (tid & 15) == 0;

    float acc[4][4] = {};
    const float scale = 0.125f;

    for (int kv0 = 0; kv0 < SEQ; kv0 += 64) {
        __syncthreads();
        {
            int rr = tid >> 2;
            int d0 = (tid & 3) << 4;
            const float* ksrc = Kg + (base + kv0 + rr) * NQKV + coff + d0;
            const float* vsrc = Vg + (base + kv0 + rr) * NQKV + coff + d0;
#pragma unroll
            for (int k = 0; k < 16; k += 4) {
                float4 v = *(const float4*)(ksrc + k);
                Ks[(d0 + k + 0) * 64 + rr] = v.x;
                Ks[(d0 + k + 1) * 64 + rr] = v.y;
                Ks[(d0 + k + 2) * 64 + rr] = v.z;
                Ks[(d0 + k + 3) * 64 + rr] = v.w;
                *(float4*)&Vs[rr * 64 + d0 + k] = *(const float4*)(vsrc + k);
            }
        }
        __syncthreads();

        float s[4][4] = {};
#pragma unroll 4
        for (int d = 0; d < 64; ++d) {
            float4 qa = *(const float4*)&Qs[d * 64 + r0];
            float4 kb = *(const float4*)&Ks[d * 64 + c0];
            float a[4]  = { qa.x, qa.y, qa.z, qa.w };
            float bb[4] = { kb.x, kb.y, kb.z, kb.w };
#pragma unroll
            for (int i = 0; i < 4; i++)
#pragma unroll
                for (int j = 0; j < 4; j++) s[i][j] += a[i] * bb[j];
        }

        float tmax[4], nm[4], om[4], psum[4];
#pragma unroll
        for (int i = 0; i < 4; i++) {
#pragma unroll
            for (int j = 0; j < 4; j++) s[i][j] *= scale;
            tmax[i] = fmaxf(fmaxf(s[i][0], s[i][1]), fmaxf(s[i][2], s[i][3]));
        }
#pragma unroll
        for (int off = 1; off < 16; off <<= 1)
#pragma unroll
            for (int i = 0; i < 4; i++)
                tmax[i] = fmaxf(tmax[i], __shfl_xor_sync(0xffffffffu, tmax[i], off));

#pragma unroll
        for (int i = 0; i < 4; i++) {
            om[i] = row_m[r0 + i];
            nm[i] = fmaxf(om[i], tmax[i]);
        }
#pragma unroll
        for (int i = 0; i < 4; i++) {
            float ps = 0.0f;
#pragma unroll
            for (int j = 0; j < 4; j++) {
                float p = __expf(s[i][j] - nm[i]);
                Ps[(c0 + j) * 68 + r0 + i] = p;
                ps += p;
            }
            psum[i] = ps;
        }
#pragma unroll
        for (int off = 1; off < 16; off <<= 1)
#pragma unroll
            for (int i = 0; i < 4; i++)
                psum[i] += __shfl_xor_sync(0xffffffffu, psum[i], off);

        if (leader) {
#pragma unroll
            for (int i = 0; i < 4; i++) {
                float corr = __expf(om[i] - nm[i]);
                row_c[r0 + i] = corr;
                row_m[r0 + i] = nm[i];
                row_l[r0 + i] = row_l[r0 + i] * corr + psum[i];
            }
        }
        __syncthreads();

#pragma unroll
        for (int i = 0; i < 4; i++) {
            float corr = row_c[r0 + i];
#pragma unroll
            for (int j = 0; j < 4; j++) acc[i][j] *= corr;
        }
#pragma unroll 4
        for (int kv = 0; kv < 64; ++kv) {
            float4 pa = *(const float4*)&Ps[kv * 68 + r0];
            float4 vb = *(const float4*)&Vs[kv * 64 + c0];
            float a[4]  = { pa.x, pa.y, pa.z, pa.w };
            float bb[4] = { vb.x, vb.y, vb.z, vb.w };
#pragma unroll
            for (int i = 0; i < 4; i++)
#pragma unroll
                for (int j = 0; j < 4; j++) acc[i][j] += a[i] * bb[j];
        }
    }

#pragma unroll
    for (int i = 0; i < 4; i++) {
        float inv = 1.0f / row_l[r0 + i];
        float4 o = make_float4(acc[i][0] * inv, acc[i][1] * inv,
                               acc[i][2] * inv, acc[i][3] * inv);
        *(float4*)&Og[(base + q0 + r0 + i) * NQKV + coff + c0] = o;
    }
}

// -------------------- launch ---------------------------------------------------
extern "C" void kernel_launch(void* const* d_in, const int* in_sizes, int n_in,
                              void* d_out, int out_size) {
    const float* x  = (const float*)d_in[0];
    const float* Wq = (const float*)d_in[1];
    const float* bq = (const float*)d_in[2];
    const float* Wk = (const float*)d_in[3];
    const float* bk = (const float*)d_in[4];
    const float* Wv = (const float*)d_in[5];
    const float* bv = (const float*)d_in[6];
    const float* Wo = (const float*)d_in[7];
    const float* bo = (const float*)d_in[8];
    float* out = (float*)d_out;

    float *Qd, *Kd, *Vd, *AOd;
    __nv_bfloat16 *xh, *xl, *aoh, *aol;
    __nv_bfloat16 *wqh, *wql, *wkh, *wkl, *wvh, *wvl, *woh, *wol;
    cudaGetSymbolAddress((void**)&Qd,  g_Q);
    cudaGetSymbolAddress((void**)&Kd,  g_K);
    cudaGetSymbolAddress((void**)&Vd,  g_V);
    cudaGetSymbolAddress((void**)&AOd, g_AO);
    cudaGetSymbolAddress((void**)&xh,  g_xh);  cudaGetSymbolAddress((void**)&xl,  g_xl);
    cudaGetSymbolAddress((void**)&aoh, g_aoh); cudaGetSymbolAddress((void**)&aol, g_aol);
    cudaGetSymbolAddress((void**)&wqh, g_wqh); cudaGetSymbolAddress((void**)&wql, g_wql);
    cudaGetSymbolAddress((void**)&wkh, g_wkh); cudaGetSymbolAddress((void**)&wkl, g_wkl);
    cudaGetSymbolAddress((void**)&wvh, g_wvh); cudaGetSymbolAddress((void**)&wvl, g_wvl);
    cudaGetSymbolAddress((void**)&woh, g_woh); cudaGetSymbolAddress((void**)&wol, g_wol);

    cudaFuncSetAttribute(attn_kernel, cudaFuncAttributeMaxDynamicSharedMemorySize,
                         ATTN_SMEM_BYTES);
    cudaFuncSetAttribute(gemm_bf16x3, cudaFuncAttributeMaxDynamicSharedMemorySize,
                         GSM_TOTAL);

    // 1) split x into bf16 hi/lo
    split_kernel<<<(NTOK * DMODEL / 2 + 255) / 256, 256>>>(x, xh, xl, NTOK * DMODEL / 2);

    // 2) transpose+split weights: W[K,N] -> Wt[N,K] bf16 hi/lo
    dim3 tb(32, 8);
    transpose_split<<<dim3(NQKV / 32, DMODEL / 32), tb>>>(Wq, wqh, wql, DMODEL, NQKV);
    transpose_split<<<dim3(NQKV / 32, DMODEL / 32), tb>>>(Wk, wkh, wkl, DMODEL, NQKV);
    transpose_split<<<dim3(NQKV / 32, DMODEL / 32), tb>>>(Wv, wvh, wvl, DMODEL, NQKV);
    transpose_split<<<dim3(DMODEL / 32, NQKV / 32), tb>>>(Wo, woh, wol, NQKV, DMODEL);

    // 3) QKV projections on HMMA: [8192,1024] @ [512,1024]^T
    dim3 gq(NQKV / 128, NTOK / 128);
    gemm_bf16x3<<<gq, 256, GSM_TOTAL>>>(xh, xl, wqh, wql, bq, Qd, DMODEL, NQKV);
    gemm_bf16x3<<<gq, 256, GSM_TOTAL>>>(xh, xl, wkh, wkl, bk, Kd, DMODEL, NQKV);
    gemm_bf16x3<<<gq, 256, GSM_TOTAL>>>(xh, xl, wvh, wvl, bv, Vd, DMODEL, NQKV);

    // 4) attention
    dim3 ga(SEQ / 64, NHEAD, 8);
    attn_kernel<<<ga, 256, ATTN_SMEM_BYTES>>>(Qd, Kd, Vd, AOd);

    // 5) split AO, 6) output projection: [8192,512] @ [1024,512]^T -> d_out
    split_kernel<<<(NTOK * NQKV / 2 + 255) / 256, 256>>>(AOd, aoh, aol, NTOK * NQKV / 2);
    dim3 go(DMODEL / 128, NTOK / 128);
    gemm_bf16x3<<<go, 256, GSM_TOTAL>>>(aoh, aol, woh, wol, bo, out, NQKV, DMODEL);
}

// round 7
// speedup vs baseline: 2.1941x; 1.6127x over previous
#include <cuda_runtime.h>
#include <cuda_bf16.h>
#include <cstdint>

#define NTOK   8192     // 8 * 1024 tokens
#define DMODEL 1024
#define NQKV   512      // H * D_K
#define SEQ    1024
#define NHEAD  8
#define DHEAD  64

// -------------------- scratch (device globals: allocation-guard safe) ----------
__device__ __nv_bfloat16 g_xh[NTOK * DMODEL], g_xl[NTOK * DMODEL];
__device__ __nv_bfloat16 g_qb[NTOK * NQKV],  g_kb[NTOK * NQKV];
__device__ __nv_bfloat16 g_vh[NTOK * NQKV],  g_vl[NTOK * NQKV];
__device__ __nv_bfloat16 g_aoh[NTOK * NQKV], g_aol[NTOK * NQKV];
__device__ __nv_bfloat16 g_wqh[NQKV * DMODEL], g_wql[NQKV * DMODEL];
__device__ __nv_bfloat16 g_wkh[NQKV * DMODEL], g_wkl[NQKV * DMODEL];
__device__ __nv_bfloat16 g_wvh[NQKV * DMODEL], g_wvl[NQKV * DMODEL];
__device__ __nv_bfloat16 g_woh[DMODEL * NQKV], g_wol[DMODEL * NQKV];

extern __shared__ unsigned char dynsmem[];

// -------------------- PTX helpers (base-target sm_80+ instructions) ------------
__device__ __forceinline__ uint32_t smem_to_u32(const void* p) {
    uint32_t a;
    asm("{ .reg .u64 t; cvta.to.shared.u64 t, %1; cvt.u32.u64 %0, t; }"
        : "=r"(a) : "l"(p));
    return a;
}
__device__ __forceinline__ void cp16(uint32_t dst, const void* src) {
    asm volatile("cp.async.ca.shared.global [%0], [%1], 16;"
                 :: "r"(dst), "l"(src) : "memory");
}
#define CP_COMMIT() asm volatile("cp.async.commit_group;" ::: "memory")
#define CP_WAIT1()  asm volatile("cp.async.wait_group 1;" ::: "memory")
#define CP_WAIT0()  asm volatile("cp.async.wait_group 0;" ::: "memory")

__device__ __forceinline__ void ldsm_x4(uint32_t* r, uint32_t addr) {
    asm volatile("ldmatrix.sync.aligned.m8n8.x4.shared.b16 {%0,%1,%2,%3}, [%4];"
                 : "=r"(r[0]), "=r"(r[1]), "=r"(r[2]), "=r"(r[3]) : "r"(addr));
}
__device__ __forceinline__ void ldsm_x2(uint32_t* r, uint32_t addr) {
    asm volatile("ldmatrix.sync.aligned.m8n8.x2.shared.b16 {%0,%1}, [%2];"
                 : "=r"(r[0]), "=r"(r[1]) : "r"(addr));
}
__device__ __forceinline__ void ldsm_x2t(uint32_t* r, uint32_t addr) {
    asm volatile("ldmatrix.sync.aligned.m8n8.x2.trans.shared.b16 {%0,%1}, [%2];"
                 : "=r"(r[0]), "=r"(r[1]) : "r"(addr));
}
__device__ __forceinline__ void mma16816(float* c, const uint32_t* a, const uint32_t* b) {
    asm volatile("mma.sync.aligned.m16n8k16.row.col.f32.bf16.bf16.f32 "
                 "{%0,%1,%2,%3}, {%4,%5,%6,%7}, {%8,%9}, {%0,%1,%2,%3};"
                 : "+f"(c[0]), "+f"(c[1]), "+f"(c[2]), "+f"(c[3])
                 : "r"(a[0]), "r"(a[1]), "r"(a[2]), "r"(a[3]),
                   "r"(b[0]), "r"(b[1]));
}
__device__ __forceinline__ uint32_t pkbf2(float lo, float hi) {
    __nv_bfloat162 t = __floats2bfloat162_rn(lo, hi);
    return reinterpret_cast<uint32_t&>(t);
}

// -------------------- pre-pass: split fp32 -> bf16 hi/lo -----------------------
__global__ void split_kernel(const float* __restrict__ src,
                             __nv_bfloat16* __restrict__ hi,
                             __nv_bfloat16* __restrict__ lo, int n2) {
    int i = blockIdx.x * blockDim.x + threadIdx.x;
    if (i < n2) {
        float2 v = ((const float2*)src)[i];
        __nv_bfloat16 h0 = __float2bfloat16(v.x);
        __nv_bfloat16 h1 = __float2bfloat16(v.y);
        __nv_bfloat16 l0 = __float2bfloat16(v.x - __bfloat162float(h0));
        __nv_bfloat16 l1 = __float2bfloat16(v.y - __bfloat162float(h1));
        ((__nv_bfloat162*)hi)[i] = __halves2bfloat162(h0, h1);
        ((__nv_bfloat162*)lo)[i] = __halves2bfloat162(l0, l1);
    }
}

// -------------------- pre-pass: W[K,N] fp32 -> Wt[N,K] bf16 hi/lo --------------
__global__ void transpose_split(const float* __restrict__ W,
                                __nv_bfloat16* __restrict__ Th,
                                __nv_bfloat16* __restrict__ Tl, int Kd, int Nd) {
    __shared__ float t[32][33];
    int k0 = blockIdx.y * 32, n0 = blockIdx.x * 32;
    for (int i = threadIdx.y; i < 32; i += 8)
        t[i][threadIdx.x] = W[(size_t)(k0 + i) * Nd + n0 + threadIdx.x];
    __syncthreads();
    for (int i = threadIdx.y; i < 32; i += 8) {
        float v = t[threadIdx.x][i];
        __nv_bfloat16 h = __float2bfloat16(v);
        __nv_bfloat16 l = __float2bfloat16(v - __bfloat162float(h));
        size_t o = (size_t)(n0 + i) * Kd + k0 + threadIdx.x;
        Th[o] = h; Tl[o] = l;
    }
}

// -------------------- bf16x3 HMMA GEMM: C = A[M,K] @ B[N,K]^T + bias -----------
// OM=0: fp32 out. OM=1: bf16 out. OM=2: bf16 hi/lo out.
#define GASTRIDE   40
#define GMAT_BYTES (128 * GASTRIDE * 2)
#define GSTAGE     (4 * GMAT_BYTES)
#define GSM_TOTAL  (2 * GSTAGE)

template <int OM>
__global__ __launch_bounds__(256)
void gemm_bf16x3(const __nv_bfloat16* __restrict__ Ah, const __nv_bfloat16* __restrict__ Al,
                 const __nv_bfloat16* __restrict__ Bh, const __nv_bfloat16* __restrict__ Bl,
                 const float* __restrict__ bias, float* __restrict__ Cf,
                 __nv_bfloat16* __restrict__ Ch, __nv_bfloat16* __restrict__ Cl,
                 int K, int N) {
    const uint32_t smem_base = smem_to_u32(dynsmem);
    const int tid  = threadIdx.x;
    const int wid  = tid >> 5, lane = tid & 31;
    const int m0 = blockIdx.y * 128, n0 = blockIdx.x * 128;

    const int mat = tid >> 6;
    const int rr  = tid & 63;
    const __nv_bfloat16* mats[4] = { Ah, Al, Bh, Bl };
    const int brow = (mat < 2) ? m0 : n0;
    const __nv_bfloat16* gsrc = mats[mat] + (size_t)brow * K;
    const uint32_t sdst = smem_base + mat * GMAT_BYTES;

    const int wm = (wid & 1) * 64;
    const int wn = (wid >> 1) * 32;
    const int aRowOff = lane & 15;
    const int aColOff = (lane & 16) ? 8 : 0;
    const int bRowOff = lane & 7;
    const int bColOff = (lane & 8) ? 8 : 0;

    float acc[4][4][4];
#pragma unroll
    for (int i = 0; i < 4; i++)
#pragma unroll
        for (int j = 0; j < 4; j++)
#pragma unroll
            for (int c = 0; c < 4; c++) acc[i][j][c] = 0.0f;

    const int nstage = K >> 5;
    {
#pragma unroll
        for (int h = 0; h < 2; ++h) {
            int row = rr + h * 64;
            const __nv_bfloat16* src = gsrc + (size_t)row * K;
            uint32_t d = sdst + row * (GASTRIDE * 2);
#pragma unroll
            for (int c = 0; c < 4; ++c) cp16(d + c * 16, src + c * 8);
        }
        CP_COMMIT();
    }

    for (int s = 0; s < nstage; ++s) {
        if (s + 1 < nstage) {
            const int k0 = (s + 1) << 5;
            const uint32_t boff = ((s + 1) & 1) * GSTAGE;
#pragma unroll
            for (int h = 0; h < 2; ++h) {
                int row = rr + h * 64;
                const __nv_bfloat16* src = gsrc + (size_t)row * K + k0;
                uint32_t d = sdst + boff + row * (GASTRIDE * 2);
#pragma unroll
                for (int c = 0; c < 4; ++c) cp16(d + c * 16, src + c * 8);
            }
            CP_COMMIT();
            CP_WAIT1();
        } else {
            CP_WAIT0();
        }
        __syncthreads();

        const uint32_t sb = smem_base + (s & 1) * GSTAGE;
        const uint32_t sbB = sb + 2 * GMAT_BYTES;
#pragma unroll
        for (int kc = 0; kc < 32; kc += 16) {
            uint32_t ah[4][4], al[4][4], bh[4][2], bl[4][2];
#pragma unroll
            for (int i = 0; i < 4; ++i) {
                uint32_t addr = sb + (wm + 16 * i + aRowOff) * (GASTRIDE * 2)
                                   + (kc + aColOff) * 2;
                ldsm_x4(ah[i], addr);
                ldsm_x4(al[i], addr + GMAT_BYTES);
            }
#pragma unroll
            for (int j = 0; j < 4; ++j) {
                uint32_t addr = sbB + (wn + 8 * j + bRowOff) * (GASTRIDE * 2)
                                    + (kc + bColOff) * 2;
                ldsm_x2(bh[j], addr);
                ldsm_x2(bl[j], addr + GMAT_BYTES);
            }
#pragma unroll
            for (int i = 0; i < 4; ++i)
#pragma unroll
                for (int j = 0; j < 4; ++j) {
                    mma16816(acc[i][j], ah[i], bh[j]);
                    mma16816(acc[i][j], ah[i], bl[j]);
                    mma16816(acc[i][j], al[i], bh[j]);
                }
        }
        __syncthreads();
    }

    const int er = lane >> 2;
    const int ec = (lane & 3) * 2;
#pragma unroll
    for (int j = 0; j < 4; ++j) {
        const int n = n0 + wn + 8 * j + ec;
        const float b0 = bias[n], b1 = bias[n + 1];
#pragma unroll
        for (int i = 0; i < 4; ++i) {
            const int m = m0 + wm + 16 * i + er;
            float v0 = acc[i][j][0] + b0, v1 = acc[i][j][1] + b1;
            float v2 = acc[i][j][2] + b0, v3 = acc[i][j][3] + b1;
            if (OM == 0) {
                *(float2*)(Cf + (size_t)m * N + n)       = make_float2(v0, v1);
                *(float2*)(Cf + (size_t)(m + 8) * N + n) = make_float2(v2, v3);
            } else {
                __nv_bfloat16 h0 = __float2bfloat16(v0), h1 = __float2bfloat16(v1);
                __nv_bfloat16 h2 = __float2bfloat16(v2), h3 = __float2bfloat16(v3);
                *(__nv_bfloat162*)(Ch + (size_t)m * N + n) = __halves2bfloat162(h0, h1);
                *(__nv_bfloat162*)(Ch + (size_t)(m + 8) * N + n) = __halves2bfloat162(h2, h3);
                if (OM == 2) {
                    __nv_bfloat16 l0 = __float2bfloat16(v0 - __bfloat162float(h0));
                    __nv_bfloat16 l1 = __float2bfloat16(v1 - __bfloat162float(h1));
                    __nv_bfloat16 l2 = __float2bfloat16(v2 - __bfloat162float(h2));
                    __nv_bfloat16 l3 = __float2bfloat16(v3 - __bfloat162float(h3));
                    *(__nv_bfloat162*)(Cl + (size_t)m * N + n) = __halves2bfloat162(l0, l1);
                    *(__nv_bfloat162*)(Cl + (size_t)(m + 8) * N + n) = __halves2bfloat162(l2, l3);
                }
            }
        }
    }
}

// -------------------- HMMA flash attention -------------------------------------
// Block = (64 q-rows, head, batch); 4 warps x 16 q-rows. BKV=64.
// S = Q@K^T on HMMA (K = n-major B operand); softmax in registers; P split
// hi/lo in registers; PV via ldmatrix.trans on row-major V (hi/lo).
#define ASTR 72   // bf16 per smem row (144 B: 8-row ldmatrix groups cover 32 banks)

__global__ __launch_bounds__(128)
void attn_mma(const __nv_bfloat16* __restrict__ Qb, const __nv_bfloat16* __restrict__ Kb,
              const __nv_bfloat16* __restrict__ Vhg, const __nv_bfloat16* __restrict__ Vlg,
              __nv_bfloat16* __restrict__ AOh, __nv_bfloat16* __restrict__ AOl) {
    __shared__ __align__(16) __nv_bfloat16 Qs[64 * ASTR];
    __shared__ __align__(16) __nv_bfloat16 Ks[64 * ASTR];
    __shared__ __align__(16) __nv_bfloat16 Vhs[64 * ASTR];
    __shared__ __align__(16) __nv_bfloat16 Vls[64 * ASTR];

    const int tid = threadIdx.x, wid = tid >> 5, lane = tid & 31;
    const int q0 = blockIdx.x * 64, h = blockIdx.y, b = blockIdx.z;
    const size_t rowbase = (size_t)b * SEQ;
    const int coff = h * DHEAD;

    const int lr = tid >> 1, lc = (tid & 1) * 32;   // loader: row, 32-col half
    {
        const __nv_bfloat16* src = Qb + (rowbase + q0 + lr) * NQKV + coff + lc;
#pragma unroll
        for (int c = 0; c < 4; ++c)
            *(uint4*)&Qs[lr * ASTR + lc + 8 * c] = *(const uint4*)(src + 8 * c);
    }
    __syncthreads();

    const uint32_t qbase = smem_to_u32(Qs), kbase = smem_to_u32(Ks);
    const uint32_t vhb = smem_to_u32(Vhs), vlb = smem_to_u32(Vls);
    const int wq = wid * 16;

    uint32_t qf[4][4];
#pragma unroll
    for (int ks = 0; ks < 4; ++ks)
        ldsm_x4(qf[ks], qbase + ((wq + (lane & 15)) * ASTR + ks * 16
                                 + ((lane & 16) ? 8 : 0)) * 2);

    float oacc[8][4];
#pragma unroll
    for (int j = 0; j < 8; ++j)
#pragma unroll
        for (int c = 0; c < 4; ++c) oacc[j][c] = 0.0f;
    float mrow0 = -1e30f, mrow1 = -1e30f, lrow0 = 0.0f, lrow1 = 0.0f;

    for (int kv0 = 0; kv0 < SEQ; kv0 += 64) {
        __syncthreads();   // all warps done reading prev K/V tiles
        {
            const size_t grow = (rowbase + kv0 + lr) * NQKV + coff + lc;
            const int so = lr * ASTR + lc;
#pragma unroll
            for (int c = 0; c < 4; ++c) {
                *(uint4*)&Ks[so + 8 * c]  = *(const uint4*)(Kb  + grow + 8 * c);
                *(uint4*)&Vhs[so + 8 * c] = *(const uint4*)(Vhg + grow + 8 * c);
                *(uint4*)&Vls[so + 8 * c] = *(const uint4*)(Vlg + grow + 8 * c);
            }
        }
        __syncthreads();

        // ---- S = Q @ K^T (fp32 acc) ----
        float s[8][4];
#pragma unroll
        for (int j = 0; j < 8; ++j)
#pragma unroll
            for (int c = 0; c < 4; ++c) s[j][c] = 0.0f;
#pragma unroll
        for (int ks = 0; ks < 4; ++ks)
#pragma unroll
            for (int j = 0; j < 8; ++j) {
                uint32_t kf[2];
                ldsm_x2(kf, kbase + ((8 * j + (lane & 7)) * ASTR + ks * 16
                                     + ((lane & 8) ? 8 : 0)) * 2);
                mma16816(s[j], qf[ks], kf);
            }

        // ---- register softmax (rows er = lane>>2 and er+8) ----
        float tmax0 = -1e30f, tmax1 = -1e30f;
#pragma unroll
        for (int j = 0; j < 8; ++j) {
            s[j][0] *= 0.125f; s[j][1] *= 0.125f; s[j][2] *= 0.125f; s[j][3] *= 0.125f;
            tmax0 = fmaxf(tmax0, fmaxf(s[j][0], s[j][1]));
            tmax1 = fmaxf(tmax1, fmaxf(s[j][2], s[j][3]));
        }
        tmax0 = fmaxf(tmax0, __shfl_xor_sync(0xffffffffu, tmax0, 1));
        tmax0 = fmaxf(tmax0, __shfl_xor_sync(0xffffffffu, tmax0, 2));
        tmax1 = fmaxf(tmax1, __shfl_xor_sync(0xffffffffu, tmax1, 1));
        tmax1 = fmaxf(tmax1, __shfl_xor_sync(0xffffffffu, tmax1, 2));

        float nm0 = fmaxf(mrow0, tmax0), nm1 = fmaxf(mrow1, tmax1);
        float corr0 = __expf(mrow0 - nm0), corr1 = __expf(mrow1 - nm1);
        mrow0 = nm0; mrow1 = nm1;
#pragma unroll
        for (int j = 0; j < 8; ++j) {
            oacc[j][0] *= corr0; oacc[j][1] *= corr0;
            oacc[j][2] *= corr1; oacc[j][3] *= corr1;
        }

        float ps0 = 0.0f, ps1 = 0.0f;
        uint32_t aH[4][4], aL[4][4];
#pragma unroll
        for (int j = 0; j < 8; ++j) {
            float p0 = __expf(s[j][0] - nm0), p1 = __expf(s[j][1] - nm0);
            float p2 = __expf(s[j][2] - nm1), p3 = __expf(s[j][3] - nm1);
            ps0 += p0 + p1; ps1 += p2 + p3;
            __nv_bfloat16 h0 = __float2bfloat16(p0), h1 = __float2bfloat16(p1);
            __nv_bfloat16 h2 = __float2bfloat16(p2), h3 = __float2bfloat16(p3);
            const int jp = j >> 1, sel = (j & 1) * 2;
            aH[jp][sel + 0] = pkbf2(__bfloat162float(h0), __bfloat162float(h1));
            aH[jp][sel + 1] = pkbf2(__bfloat162float(h2), __bfloat162float(h3));
            aL[jp][sel + 0] = pkbf2(p0 - __bfloat162float(h0), p1 - __bfloat162float(h1));
            aL[jp][sel + 1] = pkbf2(p2 - __bfloat162float(h2), p3 - __bfloat162float(h3));
        }
        ps0 += __shfl_xor_sync(0xffffffffu, ps0, 1);
        ps0 += __shfl_xor_sync(0xffffffffu, ps0, 2);
        ps1 += __shfl_xor_sync(0xffffffffu, ps1, 1);
        ps1 += __shfl_xor_sync(0xffffffffu, ps1, 2);
        lrow0 = lrow0 * corr0 + ps0;
        lrow1 = lrow1 * corr1 + ps1;

        // ---- O += P @ V (hi/lo split) ----
#pragma unroll
        for (int jd = 0; jd < 8; ++jd)
#pragma unroll
            for (int ks = 0; ks < 4; ++ks) {
                uint32_t vh2[2], vl2[2];
                uint32_t ad = ((16 * ks + (lane & 15)) * ASTR + 8 * jd) * 2;
                ldsm_x2t(vh2, vhb + ad);
                ldsm_x2t(vl2, vlb + ad);
                mma16816(oacc[jd], aH[ks], vh2);
                mma16816(oacc[jd], aH[ks], vl2);
                mma16816(oacc[jd], aL[ks], vh2);
            }
    }

    // ---- epilogue: normalize, split hi/lo, store ----
    const float inv0 = 1.0f / lrow0, inv1 = 1.0f / lrow1;
    const int er = lane >> 2, ec = (lane & 3) * 2;
    const size_t r0o = (rowbase + q0 + wq + er) * NQKV + coff;
    const size_t r1o = r0o + (size_t)8 * NQKV;
#pragma unroll
    for (int jd = 0; jd < 8; ++jd) {
        const int n = 8 * jd + ec;
        float v0 = oacc[jd][0] * inv0, v1 = oacc[jd][1] * inv0;
        float v2 = oacc[jd][2] * inv1, v3 = oacc[jd][3] * inv1;
        __nv_bfloat16 h0 = __float2bfloat16(v0), h1 = __float2bfloat16(v1);
        __nv_bfloat16 h2 = __float2bfloat16(v2), h3 = __float2bfloat16(v3);
        *(__nv_bfloat162*)&AOh[r0o + n] = __halves2bfloat162(h0, h1);
        *(__nv_bfloat162*)&AOh[r1o + n] = __halves2bfloat162(h2, h3);
        __nv_bfloat16 l0 = __float2bfloat16(v0 - __bfloat162float(h0));
        __nv_bfloat16 l1 = __float2bfloat16(v1 - __bfloat162float(h1));
        __nv_bfloat16 l2 = __float2bfloat16(v2 - __bfloat162float(h2));
        __nv_bfloat16 l3 = __float2bfloat16(v3 - __bfloat162float(h3));
        *(__nv_bfloat162*)&AOl[r0o + n] = __halves2bfloat162(l0, l1);
        *(__nv_bfloat162*)&AOl[r1o + n] = __halves2bfloat162(l2, l3);
    }
}

// -------------------- launch ---------------------------------------------------
extern "C" void kernel_launch(void* const* d_in, const int* in_sizes, int n_in,
                              void* d_out, int out_size) {
    const float* x  = (const float*)d_in[0];
    const float* Wq = (const float*)d_in[1];
    const float* bq = (const float*)d_in[2];
    const float* Wk = (const float*)d_in[3];
    const float* bk = (const float*)d_in[4];
    const float* Wv = (const float*)d_in[5];
    const float* bv = (const float*)d_in[6];
    const float* Wo = (const float*)d_in[7];
    const float* bo = (const float*)d_in[8];
    float* out = (float*)d_out;

    __nv_bfloat16 *xh, *xl, *qb, *kb, *vh, *vl, *aoh, *aol;
    __nv_bfloat16 *wqh, *wql, *wkh, *wkl, *wvh, *wvl, *woh, *wol;
    cudaGetSymbolAddress((void**)&xh,  g_xh);  cudaGetSymbolAddress((void**)&xl,  g_xl);
    cudaGetSymbolAddress((void**)&qb,  g_qb);  cudaGetSymbolAddress((void**)&kb,  g_kb);
    cudaGetSymbolAddress((void**)&vh,  g_vh);  cudaGetSymbolAddress((void**)&vl,  g_vl);
    cudaGetSymbolAddress((void**)&aoh, g_aoh); cudaGetSymbolAddress((void**)&aol, g_aol);
    cudaGetSymbolAddress((void**)&wqh, g_wqh); cudaGetSymbolAddress((void**)&wql, g_wql);
    cudaGetSymbolAddress((void**)&wkh, g_wkh); cudaGetSymbolAddress((void**)&wkl, g_wkl);
    cudaGetSymbolAddress((void**)&wvh, g_wvh); cudaGetSymbolAddress((void**)&wvl, g_wvl);
    cudaGetSymbolAddress((void**)&woh, g_woh); cudaGetSymbolAddress((void**)&wol, g_wol);

    cudaFuncSetAttribute(gemm_bf16x3<0>, cudaFuncAttributeMaxDynamicSharedMemorySize, GSM_TOTAL);
    cudaFuncSetAttribute(gemm_bf16x3<1>, cudaFuncAttributeMaxDynamicSharedMemorySize, GSM_TOTAL);
    cudaFuncSetAttribute(gemm_bf16x3<2>, cudaFuncAttributeMaxDynamicSharedMemorySize, GSM_TOTAL);

    // 1) split x into bf16 hi/lo
    split_kernel<<<(NTOK * DMODEL / 2 + 255) / 256, 256>>>(x, xh, xl, NTOK * DMODEL / 2);

    // 2) transpose+split weights
    dim3 tb(32, 8);
    transpose_split<<<dim3(NQKV / 32, DMODEL / 32), tb>>>(Wq, wqh, wql, DMODEL, NQKV);
    transpose_split<<<dim3(NQKV / 32, DMODEL / 32), tb>>>(Wk, wkh, wkl, DMODEL, NQKV);
    transpose_split<<<dim3(NQKV / 32, DMODEL / 32), tb>>>(Wv, wvh, wvl, DMODEL, NQKV);
    transpose_split<<<dim3(DMODEL / 32, NQKV / 32), tb>>>(Wo, woh, wol, NQKV, DMODEL);

    // 3) QKV projections (HMMA): Q,K -> bf16; V -> bf16 hi/lo
    dim3 gq(NQKV / 128, NTOK / 128);
    gemm_bf16x3<1><<<gq, 256, GSM_TOTAL>>>(xh, xl, wqh, wql, bq, nullptr, qb, nullptr, DMODEL, NQKV);
    gemm_bf16x3<1><<<gq, 256, GSM_TOTAL>>>(xh, xl, wkh, wkl, bk, nullptr, kb, nullptr, DMODEL, NQKV);
    gemm_bf16x3<2><<<gq, 256, GSM_TOTAL>>>(xh, xl, wvh, wvl, bv, nullptr, vh, vl, DMODEL, NQKV);

    // 4) HMMA flash attention -> AO hi/lo directly
    dim3 ga(SEQ / 64, NHEAD, 8);
    attn_mma<<<ga, 128>>>(qb, kb, vh, vl, aoh, aol);

    // 5) output projection (fp32 out): [8192,512] @ [1024,512]^T + bo
    dim3 go(DMODEL / 128, NTOK / 128);
    gemm_bf16x3<0><<<go, 256, GSM_TOTAL>>>(aoh, aol, woh, wol, bo, out, nullptr, nullptr, NQKV, DMODEL);
}